// round 4
// baseline (speedup 1.0000x reference)
#include <cuda_runtime.h>
#include <cuda_bf16.h>
#include <math.h>
#include <stdint.h>

// Problem constants
#define NN   12000      // nodes
#define NE   120000     // edges
#define FF   768        // feature width
#define PLD  4608       // node-projection row width (6 heads x 768)
#define SLOT ((size_t)FF * FF)   // elems per weight slot [768][768]

// ---------------- scratch (device globals; no allocation allowed) ------------
__device__ __nv_bfloat16 g_e1[(size_t)NE * FF];     // edge features (conv1 input)
__device__ __nv_bfloat16 g_e2[(size_t)NE * FF];     // edge features (conv2 input)
__device__ __nv_bfloat16 g_P [(size_t)NN * PLD];    // node projections (6 heads)
__device__ float         g_x [(size_t)NN * FF];     // running node features (fp32)
__device__ __nv_bfloat16 g_xb[(size_t)NN * FF];     // bf16 copy of node features
__device__ __nv_bfloat16 g_erb[(size_t)NE * 64];    // bf16 e_raw
__device__ __nv_bfloat16 g_Wt[(size_t)16 * SLOT];   // bf16 weight slots [K][768]
__device__ float         g_pool[FF];

// ---------------- PTX helpers ------------------------------------------------
__device__ __forceinline__ uint32_t s2u(const void* p) {
    return (uint32_t)__cvta_generic_to_shared(p);
}
#define CPA16(dst, src, v) \
    asm volatile("cp.async.cg.shared.global [%0], [%1], 16, %2;" \
                 :: "r"(dst), "l"(src), "r"((v) ? 16 : 0))
#define CPA_COMMIT() asm volatile("cp.async.commit_group;" ::: "memory")
#define CPA_WAIT2()  asm volatile("cp.async.wait_group 2;" ::: "memory")
#define CPA_WAIT1()  asm volatile("cp.async.wait_group 1;" ::: "memory")
#define CPA_WAIT0()  asm volatile("cp.async.wait_group 0;" ::: "memory")

__device__ __forceinline__ void ldsm4(uint32_t* r, uint32_t addr) {
    asm volatile("ldmatrix.sync.aligned.m8n8.x4.shared.b16 {%0,%1,%2,%3},[%4];"
                 : "=r"(r[0]), "=r"(r[1]), "=r"(r[2]), "=r"(r[3]) : "r"(addr));
}
__device__ __forceinline__ void ldsm4t(uint32_t* r, uint32_t addr) {
    asm volatile("ldmatrix.sync.aligned.m8n8.x4.trans.shared.b16 {%0,%1,%2,%3},[%4];"
                 : "=r"(r[0]), "=r"(r[1]), "=r"(r[2]), "=r"(r[3]) : "r"(addr));
}
__device__ __forceinline__ void mma16816(float* c, const uint32_t* a, uint32_t b0, uint32_t b1) {
    asm volatile(
        "mma.sync.aligned.m16n8k16.row.col.f32.bf16.bf16.f32 "
        "{%0,%1,%2,%3},{%4,%5,%6,%7},{%8,%9},{%0,%1,%2,%3};"
        : "+f"(c[0]), "+f"(c[1]), "+f"(c[2]), "+f"(c[3])
        : "r"(a[0]), "r"(a[1]), "r"(a[2]), "r"(a[3]), "r"(b0), "r"(b1));
}
__device__ __forceinline__ uint32_t pk2(float a, float b) {
    __nv_bfloat162 h = __floats2bfloat162_rn(a, b);
    return *(uint32_t*)&h;
}
__device__ __forceinline__ float ubf(const __nv_bfloat16& v) { return __bfloat162float(v); }
__device__ __forceinline__ float sigm(float t) { return 1.f / (1.f + __expf(-t)); }

// ---------------- fused pipelined mma.sync GEMM -------------------------------
// smem: A tile 128x32 (row stride 80B), B tile 32x128 (row stride 272B),
// 4 buffers, prefetch distance 3, ONE __syncthreads per K-stage.
enum { EPI_STORE = 0, EPI_TANH = 1, EPI_GATE = 2, EPI_FMSG = 3 };

#define A_TB  10240                    // 128*40*2
#define B_TB  8704                     // 32*136*2
#define SMEM_BYTES (4 * (A_TB + B_TB)) // 75776

struct GArgs {
    const __nv_bfloat16* A;    int lda; int M; int K;
    const __nv_bfloat16* B;    const __nv_bfloat16* B2; int ldb;  // [K][768]
    const float*         bias; const float* bias2;
    const __nv_bfloat16* Pdf;  const __nv_bfloat16* Psf;  // f-head slices (ld PLD)
    const __nv_bfloat16* Pds;  const __nv_bfloat16* Pss;  // s-head slices
    const int*           dst;  const int* srcI;
    const __nv_bfloat16* aux;  // GATE: e_in (ld 768)
    __nv_bfloat16*       outb; int ldo;
    float*               atom; // FMSG: fp32 node accumulator (ld 768)
    int                  multi;    // node-pass: slots merged into grid.x
    int                  slotBase;
};

template<int EPI>
__global__ void __launch_bounds__(256, 2) gemm_k(GArgs g) {
    extern __shared__ char smem_raw[];
    const uint32_t sb = s2u(smem_raw);

    const int tid = threadIdx.x, lane = tid & 31, warp = tid >> 5;
    const int bm = blockIdx.y * 128;

    // decode N mapping
    int bn, outCol;                 // bn = feature col of tile col 0
    const __nv_bfloat16* Bp = g.B;
    if (EPI == EPI_STORE && g.multi) {
        int idx = blockIdx.x / 6, nb = blockIdx.x % 6;
        int slot = g.slotBase + (idx >> 1) * 3 + (idx & 1);
        Bp += (size_t)slot * SLOT;
        bn = nb * 128;
        outCol = idx * 768 + nb * 128;
    } else if (EPI == EPI_FMSG) {
        bn = blockIdx.x * 64;       // 64 feature cols, two heads side by side
        outCol = bn;
    } else {
        bn = blockIdx.x * 128;
        outCol = bn;
    }

    // ---- loader mapping: 1024 chunks of 16B (A 512 + B 512) per stage -------
    const int ar0 = tid >> 2, akc = tid & 3;
    const int br0 = tid >> 4, bkc = tid & 15;
    const uint32_t adst0 = ar0 * 80 + akc * 16;
    const uint32_t adst1 = adst0 + 64 * 80;
    const uint32_t bdst0 = br0 * 272 + bkc * 16;
    const uint32_t bdst1 = bdst0 + 16 * 272;
    const bool av0 = (bm + ar0) < g.M;
    const bool av1 = (bm + ar0 + 64) < g.M;
    const __nv_bfloat16* asrc0 = g.A + (size_t)min(bm + ar0,      g.M - 1) * g.lda + akc * 8;
    const __nv_bfloat16* asrc1 = g.A + (size_t)min(bm + ar0 + 64, g.M - 1) * g.lda + akc * 8;
    const __nv_bfloat16* bbase;
    int bcol;
    if (EPI == EPI_FMSG) { bbase = (bkc < 8) ? g.B : g.B2; bcol = bn + (bkc & 7) * 8; }
    else                 { bbase = Bp;                     bcol = bn + bkc * 8; }
    const __nv_bfloat16* bsrc0 = bbase + (size_t)br0        * g.ldb + bcol;
    const __nv_bfloat16* bsrc1 = bbase + (size_t)(br0 + 16) * g.ldb + bcol;
    const size_t bstep = (size_t)32 * g.ldb;

    auto load_stage = [&](int buf) {
        const uint32_t Ab = sb + buf * A_TB;
        const uint32_t Bb = sb + 4 * A_TB + buf * B_TB;
        CPA16(Ab + adst0, asrc0, av0);
        CPA16(Ab + adst1, asrc1, av1);
        CPA16(Bb + bdst0, bsrc0, true);
        CPA16(Bb + bdst1, bsrc1, true);
        asrc0 += 32; asrc1 += 32; bsrc0 += bstep; bsrc1 += bstep;
        CPA_COMMIT();
    };

    const int S = g.K >> 5;
    const int wm = (warp & 1) * 64;
    const int wn = (warp >> 1) * 32;

    float acc[4][4][4];
    #pragma unroll
    for (int i = 0; i < 4; i++)
        #pragma unroll
        for (int j = 0; j < 4; j++)
            #pragma unroll
            for (int k = 0; k < 4; k++) acc[i][j][k] = 0.f;

    const int pre = S < 3 ? S : 3;
    for (int p = 0; p < pre; p++) load_stage(p);

    for (int s = 0; s < S; s++) {
        const int rem = S - s - 1;
        if (rem >= 2)      CPA_WAIT2();
        else if (rem == 1) CPA_WAIT1();
        else               CPA_WAIT0();
        __syncthreads();                       // single barrier per stage
        if (s + 3 < S) load_stage((s + 3) & 3);

        const uint32_t Ab = sb + (s & 3) * A_TB;
        const uint32_t Bb = sb + 4 * A_TB + (s & 3) * B_TB;
        #pragma unroll
        for (int ks = 0; ks < 2; ks++) {
            uint32_t a[4][4], b[2][4];
            #pragma unroll
            for (int mi = 0; mi < 4; mi++)
                ldsm4(a[mi], Ab + ((wm + mi * 16 + (lane & 15)) * 40 + ks * 16 + (lane >> 4) * 8) * 2);
            #pragma unroll
            for (int np = 0; np < 2; np++)
                ldsm4t(b[np], Bb + ((ks * 16 + (lane & 15)) * 136 + wn + np * 16 + (lane >> 4) * 8) * 2);
            #pragma unroll
            for (int mi = 0; mi < 4; mi++)
                #pragma unroll
                for (int ni = 0; ni < 4; ni++)
                    mma16816(acc[mi][ni], a[mi], b[ni >> 1][(ni & 1) * 2], b[ni >> 1][(ni & 1) * 2 + 1]);
        }
    }

    // ------------------------------ epilogue ------------------------------
    const int tig = lane & 3;
    const int gid = lane >> 2;

    if (EPI == EPI_FMSG) {
        // tile cols 0-63 = f-head, 64-127 = s-head (same feature cols bn..bn+63)
        __syncthreads();                       // protect smem reuse vs mainloop
        float* sigb = (float*)smem_raw;        // [128][66] floats
        const bool isF = (warp >> 1) < 2;
        const int colBase = isF ? wn : (wn - 64);
        if (isF) {
            #pragma unroll
            for (int mi = 0; mi < 4; mi++) {
                #pragma unroll
                for (int h = 0; h < 2; h++) {
                    const int rloc = wm + mi * 16 + gid + h * 8;
                    const int rr = bm + rloc;
                    int di = 0, si = 0;
                    if (rr < g.M) { di = g.dst[rr]; si = g.srcI[rr]; }
                    #pragma unroll
                    for (int ni = 0; ni < 4; ni++) {
                        const int cl = colBase + ni * 8 + tig * 2;
                        const int c  = bn + cl;
                        float s0 = 0.f, s1 = 0.f;
                        if (rr < g.M) {
                            float t0 = acc[mi][ni][h*2]   + ubf(g.Pdf[(size_t)di*PLD + c])
                                     + ubf(g.Psf[(size_t)si*PLD + c]) + g.bias[c];
                            float t1 = acc[mi][ni][h*2+1] + ubf(g.Pdf[(size_t)di*PLD + c+1])
                                     + ubf(g.Psf[(size_t)si*PLD + c+1]) + g.bias[c+1];
                            s0 = sigm(t0); s1 = sigm(t1);
                        }
                        *(float2*)&sigb[rloc * 66 + cl] = make_float2(s0, s1);
                    }
                }
            }
        }
        __syncthreads();
        if (!isF) {
            #pragma unroll
            for (int mi = 0; mi < 4; mi++) {
                #pragma unroll
                for (int h = 0; h < 2; h++) {
                    const int rloc = wm + mi * 16 + gid + h * 8;
                    const int rr = bm + rloc;
                    if (rr >= g.M) continue;
                    const int di = g.dst[rr], si = g.srcI[rr];
                    #pragma unroll
                    for (int ni = 0; ni < 4; ni++) {
                        const int cl = colBase + ni * 8 + tig * 2;
                        const int c  = bn + cl;
                        float t0 = acc[mi][ni][h*2]   + ubf(g.Pds[(size_t)di*PLD + c])
                                 + ubf(g.Pss[(size_t)si*PLD + c]) + g.bias2[c];
                        float t1 = acc[mi][ni][h*2+1] + ubf(g.Pds[(size_t)di*PLD + c+1])
                                 + ubf(g.Pss[(size_t)si*PLD + c+1]) + g.bias2[c+1];
                        float2 sg = *(float2*)&sigb[rloc * 66 + cl];
                        float m0 = fmaxf(t0, 0.f) * sg.x;
                        float m1 = fmaxf(t1, 0.f) * sg.y;
                        atomicAdd((float2*)(g.atom + (size_t)di * 768 + c), make_float2(m0, m1));
                    }
                }
            }
        }
        return;
    }

    #pragma unroll
    for (int mi = 0; mi < 4; mi++) {
        #pragma unroll
        for (int h = 0; h < 2; h++) {
            const int rr = bm + wm + mi * 16 + gid + h * 8;
            if (rr >= g.M) continue;
            int di = 0, si = 0;
            if (EPI == EPI_GATE) { di = g.dst[rr]; si = g.srcI[rr]; }
            #pragma unroll
            for (int ni = 0; ni < 4; ni++) {
                const int cl = wn + ni * 8 + tig * 2;
                const float v0 = acc[mi][ni][h * 2];
                const float v1 = acc[mi][ni][h * 2 + 1];
                if (EPI == EPI_STORE) {
                    *(uint32_t*)(g.outb + (size_t)rr * g.ldo + outCol + cl) = pk2(v0, v1);
                } else if (EPI == EPI_TANH) {
                    const int c = bn + cl;
                    *(uint32_t*)(g.outb + (size_t)rr * g.ldo + c) =
                        pk2(tanhf(v0 + g.bias[c]), tanhf(v1 + g.bias[c + 1]));
                } else { // EPI_GATE
                    const int c = bn + cl;
                    float t0 = v0 + ubf(g.Pdf[(size_t)di*PLD + c])
                                  + ubf(g.Psf[(size_t)si*PLD + c]) + g.bias[c];
                    float t1 = v1 + ubf(g.Pdf[(size_t)di*PLD + c+1])
                                  + ubf(g.Psf[(size_t)si*PLD + c+1]) + g.bias[c+1];
                    float a0 = ubf(g.aux[(size_t)rr * 768 + c]);
                    float a1 = ubf(g.aux[(size_t)rr * 768 + c + 1]);
                    *(uint32_t*)(g.outb + (size_t)rr * 768 + c) =
                        pk2(a0 * (1.f + sigm(t0)), a1 * (1.f + sigm(t1)));
                }
            }
        }
    }
}

// ---------------- small kernels ----------------------------------------------
__global__ void cvt_x_kernel(const float* __restrict__ x) {
    int i = blockIdx.x * blockDim.x + threadIdx.x;
    const int n4 = NN * FF / 4;
    if (i < n4) {
        float4 v = ((const float4*)x)[i];
        ((float4*)g_x)[i] = v;
        ((__nv_bfloat162*)g_xb)[i * 2]     = __floats2bfloat162_rn(v.x, v.y);
        ((__nv_bfloat162*)g_xb)[i * 2 + 1] = __floats2bfloat162_rn(v.z, v.w);
    }
    if (i < FF) g_pool[i] = 0.f;
}
__global__ void cvt_bf16_kernel(const float* __restrict__ s, __nv_bfloat16* __restrict__ d, int n4) {
    int i = blockIdx.x * blockDim.x + threadIdx.x;
    if (i < n4) {
        float4 v = ((const float4*)s)[i];
        ((__nv_bfloat162*)d)[i * 2]     = __floats2bfloat162_rn(v.x, v.y);
        ((__nv_bfloat162*)d)[i * 2 + 1] = __floats2bfloat162_rn(v.z, v.w);
    }
}
// convert all 16 weight slots in one launch
__global__ void cvt_w_kernel(const float* Wf1, const float* Ws1, const float* We1,
                             const float* Wf2, const float* Ws2, const float* Wp) {
    int i = blockIdx.x * blockDim.x + threadIdx.x;    // float4 index
    const int big = (int)(3 * SLOT / 4);              // 442368 per weight matrix
    const float* s;
    __nv_bfloat16* d;
    void* pWtv; 
    if (i < 5 * big) {
        int w = i / big, r = i - w * big;
        const float* srcs[5] = { Wf1, Ws1, We1, Wf2, Ws2 };
        s = srcs[w] + (size_t)r * 4;
        d = g_Wt + (size_t)w * 3 * SLOT + (size_t)r * 4;
    } else {
        int r = i - 5 * big;
        if (r >= 64 * FF / 4) return;
        s = Wp + (size_t)r * 4;
        d = g_Wt + (size_t)15 * SLOT + (size_t)r * 4;
    }
    float4 v = *(const float4*)s;
    *(__nv_bfloat162*)d       = __floats2bfloat162_rn(v.x, v.y);
    *(__nv_bfloat162*)(d + 2) = __floats2bfloat162_rn(v.z, v.w);
    (void)pWtv;
}
__global__ void pool_kernel() {
    int c  = blockIdx.x * blockDim.x + threadIdx.x;
    int r0 = blockIdx.y * 240;
    int r1 = min(r0 + 240, NN);
    float s = 0.f;
    for (int r = r0; r < r1; r++) s += g_x[(size_t)r * FF + c];
    atomicAdd(&g_pool[c], s);
}
__global__ void final_kernel(const float* __restrict__ Wd, const float* __restrict__ bd,
                             float* __restrict__ out) {
    int l = threadIdx.x;
    float logit = -1e30f;
    if (l < 16) {
        float s = bd[l];
        #pragma unroll 8
        for (int f = 0; f < FF; f++) s += g_pool[f] * Wd[f * 16 + l];
        logit = s;
    }
    float m = logit;
    #pragma unroll
    for (int o = 16; o > 0; o >>= 1) m = fmaxf(m, __shfl_xor_sync(0xffffffffu, m, o));
    float e = (l < 16) ? __expf(logit - m) : 0.f;
    float sum = e;
    #pragma unroll
    for (int o = 16; o > 0; o >>= 1) sum += __shfl_xor_sync(0xffffffffu, sum, o);
    if (l < 16) out[l] = e / sum;
}

// ---------------- host orchestration ------------------------------------------
extern "C" void kernel_launch(void* const* d_in, const int* in_sizes, int n_in,
                              void* d_out, int out_size) {
    (void)in_sizes; (void)n_in; (void)out_size;
    const float* x     = (const float*)d_in[0];
    const float* e_raw = (const float*)d_in[1];
    const int*   src   = (const int*)d_in[2];
    const int*   dst   = (const int*)d_in[3];
    const float* W_pre = (const float*)d_in[4];
    const float* b_pre = (const float*)d_in[5];
    const float* Wf1 = (const float*)d_in[6],  *bf1 = (const float*)d_in[7];
    const float* Ws1 = (const float*)d_in[8],  *bs1 = (const float*)d_in[9];
    const float* We1 = (const float*)d_in[10], *be1 = (const float*)d_in[11];
    const float* Wf2 = (const float*)d_in[12], *bf2 = (const float*)d_in[13];
    const float* Ws2 = (const float*)d_in[14], *bs2 = (const float*)d_in[15];
    const float* Wd  = (const float*)d_in[18], *bd  = (const float*)d_in[19];

    void *pe1v, *pe2v, *pPv, *pxv, *pxbv, *perbv, *pWtv;
    cudaGetSymbolAddress(&pe1v,  g_e1);
    cudaGetSymbolAddress(&pe2v,  g_e2);
    cudaGetSymbolAddress(&pPv,   g_P);
    cudaGetSymbolAddress(&pxv,   g_x);
    cudaGetSymbolAddress(&pxbv,  g_xb);
    cudaGetSymbolAddress(&perbv, g_erb);
    cudaGetSymbolAddress(&pWtv,  g_Wt);
    __nv_bfloat16* pe1  = (__nv_bfloat16*)pe1v;
    __nv_bfloat16* pe2  = (__nv_bfloat16*)pe2v;
    __nv_bfloat16* pP   = (__nv_bfloat16*)pPv;
    float*         px   = (float*)pxv;
    __nv_bfloat16* pxb  = (__nv_bfloat16*)pxbv;
    __nv_bfloat16* perb = (__nv_bfloat16*)perbv;
    __nv_bfloat16* pWt  = (__nv_bfloat16*)pWtv;

    cudaFuncSetAttribute(gemm_k<EPI_STORE>, cudaFuncAttributeMaxDynamicSharedMemorySize, SMEM_BYTES);
    cudaFuncSetAttribute(gemm_k<EPI_TANH>,  cudaFuncAttributeMaxDynamicSharedMemorySize, SMEM_BYTES);
    cudaFuncSetAttribute(gemm_k<EPI_GATE>,  cudaFuncAttributeMaxDynamicSharedMemorySize, SMEM_BYTES);
    cudaFuncSetAttribute(gemm_k<EPI_FMSG>,  cudaFuncAttributeMaxDynamicSharedMemorySize, SMEM_BYTES);

    const dim3 blk(256);
    const dim3 gE(6,  (NE + 127) / 128);   // full-width edge passes
    const dim3 gF(12, (NE + 127) / 128);   // fused f+s edge passes (64 cols/head)
    const dim3 gN1(36, (NN + 127) / 128);
    const dim3 gN2(24, (NN + 127) / 128);
    auto slot = [&](int i) { return pWt + (size_t)i * SLOT; };

    // (1) x -> g_x + g_xb, zero pool   (2) e_raw -> bf16   (3) all weights -> bf16
    cvt_x_kernel<<<(NN * FF / 4 + 255) / 256, blk>>>(x);
    cvt_bf16_kernel<<<(NE * 64 / 4 + 255) / 256, blk>>>(e_raw, perb, NE * 64 / 4);
    {
        const int tot4 = 5 * (int)(3 * SLOT / 4) + 64 * FF / 4;
        cvt_w_kernel<<<(tot4 + 255) / 256, blk>>>(Wf1, Ws1, We1, Wf2, Ws2, W_pre);
    }

    // (4) pre-edge: e1 = tanh(e_raw @ W_pre + b_pre)
    {
        GArgs a = {};
        a.A = perb; a.lda = 64; a.M = NE; a.K = 64;
        a.B = slot(15); a.ldb = 768; a.bias = b_pre;
        a.outb = pe1; a.ldo = 768;
        gemm_k<EPI_TANH><<<gE, blk, SMEM_BYTES>>>(a);
    }

    auto node_pass = [&](int slotBase, dim3 grid) {
        GArgs a = {};
        a.A = pxb; a.lda = 768; a.M = NN; a.K = 768;
        a.B = pWt; a.ldb = 768;
        a.outb = pP; a.ldo = PLD;
        a.multi = 1; a.slotBase = slotBase;
        gemm_k<EPI_STORE><<<grid, blk, SMEM_BYTES>>>(a);
    };
    auto fused_pass = [&](const __nv_bfloat16* eIn, int fSlot, int sSlot,
                          const float* bf, const float* bs) {
        GArgs a = {};
        a.A = eIn; a.lda = 768; a.M = NE; a.K = 768;
        a.B = slot(fSlot); a.B2 = slot(sSlot); a.ldb = 768;
        a.bias = bf; a.bias2 = bs;
        a.Pdf = pP + 0;    a.Psf = pP + 768;    // f-head projections
        a.Pds = pP + 1536; a.Pss = pP + 2304;   // s-head projections
        a.dst = dst; a.srcI = src; a.atom = px;
        gemm_k<EPI_FMSG><<<gF, blk, SMEM_BYTES>>>(a);
    };

    // (5) conv1 node projections: slots {0,1,3,4,6,7} -> P cols idx*768
    node_pass(0, gN1);

    // (6) conv1 fused edge pass: x += scatter(relu(s) * sigmoid(f))   [ncu target]
    fused_pass(pe1, 2, 5, bf1, bs1);

    // (7) conv1 gate pass: e2 = e1 * (1 + sigmoid(e-head))
    {
        GArgs a = {};
        a.A = pe1; a.lda = 768; a.M = NE; a.K = 768;
        a.B = slot(8); a.ldb = 768; a.bias = be1;
        a.Pdf = pP + 3072; a.Psf = pP + 3840;
        a.dst = dst; a.srcI = src;
        a.aux = pe1; a.outb = pe2; a.ldo = 768;
        gemm_k<EPI_GATE><<<gE, blk, SMEM_BYTES>>>(a);
    }

    // (8) refresh bf16 node features (x1)
    cvt_bf16_kernel<<<(NN * FF / 4 + 255) / 256, blk>>>(px, pxb, NN * FF / 4);

    // (9) conv2 node projections: slots {9,10,12,13}
    node_pass(9, gN2);

    // (10) conv2 fused edge pass (gate head unused by reference -> skipped)
    fused_pass(pe2, 11, 14, bf2, bs2);

    // (11,12) pool + dense + softmax
    pool_kernel<<<dim3(3, 50), blk>>>();
    final_kernel<<<1, 32>>>(Wd, bd, (float*)d_out);
}